// round 2
// baseline (speedup 1.0000x reference)
#include <cuda_runtime.h>
#include <cstdint>
#include <cstddef>
#include <math.h>

// ---------------------------------------------------------------------------
// Scratch (device globals -- no allocation allowed)
// ---------------------------------------------------------------------------
__device__ int   g_knn1[2 * 4096 * 16];
__device__ int   g_knn2[2 * 2048 * 16];
__device__ float g_ch1 [2 * 4096 * 128];
__device__ float g_res1[2 * 4096 * 128];

// ---------------------------------------------------------------------------
// KNN: one warp per center. Lane-partitioned scan, per-lane top-16 kept as
// unsorted u64 keys ((dist_bits<<32)|idx) with tracked max (replace-max).
// Final warp merge: 16 rounds of warp-wide argmin. Key packing reproduces
// jax.lax.top_k's stable ordering (dist asc, then index asc) exactly.
// Centers are rows n*2*pstride of the original pos array; points are rows
// j*pstride. Indices written are in point-set coordinates (0..n_in-1).
// ---------------------------------------------------------------------------
__global__ void knn_kernel(const float* __restrict__ pos, int pstride,
                           int n_in, int n_out, int* __restrict__ knn_out)
{
    const int warp = threadIdx.x >> 5;
    const int lane = threadIdx.x & 31;
    const int center = blockIdx.x * (blockDim.x >> 5) + warp;
    if (center >= 2 * n_out) return;
    const int b = center / n_out;
    const int n = center % n_out;

    const float* posb = pos + (size_t)b * 8192 * 3;
    const float* cp = posb + (size_t)(n * 2 * pstride) * 3;
    const float cx = cp[0], cy = cp[1], cz = cp[2];

    unsigned long long keys[16];
#pragma unroll
    for (int i = 0; i < 16; i++) keys[i] = ~0ull;
    unsigned long long maxk = ~0ull;
    int maxp = 0;

    for (int j = lane; j < n_in; j += 32) {
        const float* p = posb + (size_t)(j * pstride) * 3;
        float px = __ldg(p), py = __ldg(p + 1), pz = __ldg(p + 2);
        float dx = cx - px, dy = cy - py, dz = cz - pz;
        // match reference: square each (rounded), then left-to-right sum, no FMA
        float d = __fadd_rn(__fadd_rn(__fmul_rn(dx, dx), __fmul_rn(dy, dy)),
                            __fmul_rn(dz, dz));
        unsigned long long key =
            ((unsigned long long)__float_as_uint(d) << 32) | (unsigned)j;
        if (key < maxk) {
#pragma unroll
            for (int i = 0; i < 16; i++) if (i == maxp) keys[i] = key;
            maxk = keys[0]; maxp = 0;
#pragma unroll
            for (int i = 1; i < 16; i++) {
                if (keys[i] > maxk) { maxk = keys[i]; maxp = i; }
            }
        }
    }

    // warp merge: 16 rounds of global argmin
    int* outp = knn_out + (size_t)center * 16;
    for (int r = 0; r < 16; r++) {
        unsigned long long mymin = keys[0];
        int mp = 0;
#pragma unroll
        for (int i = 1; i < 16; i++) {
            if (keys[i] < mymin) { mymin = keys[i]; mp = i; }
        }
        unsigned long long wmin = mymin;
#pragma unroll
        for (int off = 16; off; off >>= 1) {
            unsigned long long o = __shfl_xor_sync(0xffffffffu, wmin, off);
            if (o < wmin) wmin = o;
        }
        unsigned mask = __ballot_sync(0xffffffffu, mymin == wmin);
        int winner = __ffs(mask) - 1;
        if (lane == winner) {
#pragma unroll
            for (int i = 0; i < 16; i++) if (i == mp) keys[i] = ~0ull;
        }
        if (lane == 0) outp[r] = (int)(unsigned)(wmin & 0xffffffffull);
    }
}

// ---------------------------------------------------------------------------
// Gathered conv as tiled SGEMM + fused bias + LayerNorm + SiLU (+ residual).
// A[m][k*CIN+c] = ch[b, knn[m][k], c] gathered on the fly; B = W [128][16*CIN].
// BN = 128 = full Cout, so each block owns complete output rows -> LN fused.
// Double-buffered smem tiles, 8x8 (or 4x8) register microtile, 128 threads.
// ---------------------------------------------------------------------------
template <int CIN, int BM, int TM, bool HAS_RES>
__global__ void __launch_bounds__(128, 1)
gconv_kernel(const float* __restrict__ ch, const int* __restrict__ knn,
             const float* __restrict__ W, const float* __restrict__ bias,
             const float* __restrict__ gamma, const float* __restrict__ beta,
             const float* __restrict__ res_in, float* __restrict__ out,
             int n_in, int n_out)
{
    constexpr int BN = 128, BK = 16, TN = 8;
    constexpr int SA = BM + 4;          // padded A stride (k-major: [BK][BM])
    constexpr int SB = BN + 4;          // padded B stride ([BK][BN])
    constexpr int F = BM * BK / 128;    // A floats loaded per thread
    constexpr int TPR = BK / F;         // threads per A row
    constexpr int KD = 16 * CIN;
    constexpr int ITERS = CIN;          // KD / BK
    constexpr int LOADSZ = BK * SA + BK * SB;
    constexpr int SMEMSZ = (2 * LOADSZ > BM * BN) ? 2 * LOADSZ : BM * BN;
    __shared__ float sm[SMEMSZ];

    const int tid = threadIdx.x;
    const int m_base = blockIdx.x * BM;
    const int b = m_base / n_out;               // BM divides n_out
    const int tc = tid & 15;                    // 16 col groups
    const int tr = tid >> 4;                    // 8 row groups (BM/8 = TM)
    const int arow = tid / TPR;
    const int aoff = (tid % TPR) * F;
    const int* knnrow = knn + (size_t)(m_base + arow) * 16;
    const float* chb = ch + (size_t)b * n_in * CIN;
    const float* Wr = W + (size_t)tid * KD;     // thread t owns output col t

    float acc[TM][TN];
#pragma unroll
    for (int i = 0; i < TM; i++)
#pragma unroll
        for (int j = 0; j < TN; j++) acc[i][j] = 0.0f;

    float ra[F], rb[16];

    auto loadA = [&](int it) {
        int kn = (it * BK) / CIN;
        int c0 = (it * BK) % CIN;
        int j = __ldg(&knnrow[kn]);
        const float* src = chb + (size_t)j * CIN + c0 + aoff;
#pragma unroll
        for (int i = 0; i < F; i += 4) {
            float4 v = *(const float4*)(src + i);
            ra[i] = v.x; ra[i + 1] = v.y; ra[i + 2] = v.z; ra[i + 3] = v.w;
        }
    };
    auto loadB = [&](int it) {
        const float* src = Wr + it * BK;
#pragma unroll
        for (int i = 0; i < 16; i += 4) {
            float4 v = *(const float4*)(src + i);
            rb[i] = v.x; rb[i + 1] = v.y; rb[i + 2] = v.z; rb[i + 3] = v.w;
        }
    };
    auto storeAB = [&](int buf) {
        float* As = sm + buf * LOADSZ;
        float* Bs = As + BK * SA;
#pragma unroll
        for (int i = 0; i < F; i++) As[(aoff + i) * SA + arow] = ra[i];
#pragma unroll
        for (int i = 0; i < 16; i++) Bs[i * SB + tid] = rb[i];
    };

    loadA(0); loadB(0); storeAB(0);
    __syncthreads();
    int cur = 0;

    for (int it = 0; it < ITERS; ++it) {
        if (it + 1 < ITERS) { loadA(it + 1); loadB(it + 1); }
        const float* As = sm + cur * LOADSZ;
        const float* Bs = As + BK * SA;
#pragma unroll
        for (int kk = 0; kk < BK; ++kk) {
            float a[TM], bv[TN];
#pragma unroll
            for (int i = 0; i < TM; i += 4) {
                float4 v = *(const float4*)(As + kk * SA + tr * TM + i);
                a[i] = v.x; a[i + 1] = v.y; a[i + 2] = v.z; a[i + 3] = v.w;
            }
#pragma unroll
            for (int i = 0; i < TN; i += 4) {
                float4 v = *(const float4*)(Bs + kk * SB + tc * TN + i);
                bv[i] = v.x; bv[i + 1] = v.y; bv[i + 2] = v.z; bv[i + 3] = v.w;
            }
#pragma unroll
            for (int i = 0; i < TM; i++)
#pragma unroll
                for (int j = 0; j < TN; j++) acc[i][j] += a[i] * bv[j];
        }
        if (it + 1 < ITERS) {
            storeAB(cur ^ 1);
            __syncthreads();
            cur ^= 1;
        }
    }

    // ---- epilogue: bias + LayerNorm + SiLU (+ residual) ----
    __syncthreads();                    // done with A/B tiles; reuse as Cs
    float* Cs = sm;
#pragma unroll
    for (int i = 0; i < TM; i++)
#pragma unroll
        for (int j = 0; j < TN; j++)
            Cs[(tr * TM + i) * BN + tc * TN + j] = acc[i][j];
    __syncthreads();

    const int w = tid >> 5, lane = tid & 31;
    float4 bb = *(const float4*)(bias + lane * 4);
    float4 gg = *(const float4*)(gamma + lane * 4);
    float4 be = *(const float4*)(beta + lane * 4);

    for (int r = w; r < BM; r += 4) {
        float4 x = *(float4*)(Cs + r * BN + lane * 4);
        x.x += bb.x; x.y += bb.y; x.z += bb.z; x.w += bb.w;

        float s = x.x + x.y + x.z + x.w;
#pragma unroll
        for (int off = 16; off; off >>= 1) s += __shfl_xor_sync(~0u, s, off);
        float mu = s * (1.0f / 128.0f);
        float d0 = x.x - mu, d1 = x.y - mu, d2v = x.z - mu, d3 = x.w - mu;
        float s2 = d0 * d0 + d1 * d1 + d2v * d2v + d3 * d3;
#pragma unroll
        for (int off = 16; off; off >>= 1) s2 += __shfl_xor_sync(~0u, s2, off);
        float rstd = rsqrtf(s2 * (1.0f / 128.0f) + 1e-5f);

        float y0 = d0 * rstd * gg.x + be.x;
        float y1 = d1 * rstd * gg.y + be.y;
        float y2 = d2v * rstd * gg.z + be.z;
        float y3 = d3 * rstd * gg.w + be.w;
        float4 o4;
        o4.x = y0 / (1.0f + expf(-y0));
        o4.y = y1 / (1.0f + expf(-y1));
        o4.z = y2 / (1.0f + expf(-y2));
        o4.w = y3 / (1.0f + expf(-y3));

        const int m = m_base + r;
        if (HAS_RES) {
            const int nn = m % n_out;
            const float4 rr = *(const float4*)(
                res_in + ((size_t)b * (2 * n_out) + 2 * nn) * BN + lane * 4);
            o4.x += rr.x; o4.y += rr.y; o4.z += rr.z; o4.w += rr.w;
        }
        *(float4*)(out + (size_t)m * BN + lane * 4) = o4;
    }
}

// ---------------------------------------------------------------------------
// Residual path (stage 1): res1[b,n,:] = ch[b,2n,:] @ Wres + bres
// Wres [64,128] cached in smem, thread t owns output col t, 64 rows/block.
// ---------------------------------------------------------------------------
__global__ void __launch_bounds__(128) res_kernel(
    const float* __restrict__ ch, const float* __restrict__ Wres,
    const float* __restrict__ bres, float* __restrict__ res1)
{
    __shared__ float s_w[64 * 128];
    __shared__ float s_ch[8][64];
    const int tid = threadIdx.x;
    const int m_base = blockIdx.x * 64;
    const int b = m_base / 4096;
    const int n_base = m_base % 4096;

    for (int i = tid; i < 64 * 128 / 4; i += 128)
        ((float4*)s_w)[i] = ((const float4*)Wres)[i];
    __syncthreads();

    const float bias = __ldg(&bres[tid]);
    const int rr = tid >> 4, q = tid & 15;

    for (int g = 0; g < 8; g++) {
        const float* src = ch +
            ((size_t)b * 8192 + 2 * (n_base + g * 8 + rr)) * 64 + q * 4;
        *(float4*)&s_ch[rr][q * 4] = *(const float4*)src;
        __syncthreads();
        float acc[8];
#pragma unroll
        for (int t = 0; t < 8; t++) acc[t] = bias;
        for (int c = 0; c < 64; c++) {
            float wv = s_w[c * 128 + tid];
#pragma unroll
            for (int t = 0; t < 8; t++) acc[t] += s_ch[t][c] * wv;
        }
#pragma unroll
        for (int t = 0; t < 8; t++)
            res1[(size_t)(m_base + g * 8 + t) * 128 + tid] = acc[t];
        __syncthreads();
    }
}

// ---------------------------------------------------------------------------
// pos output: pos[:, ::4, :] -> d_out[0 : 2*2048*3)
// ---------------------------------------------------------------------------
__global__ void poscopy_kernel(const float* __restrict__ pos,
                               float* __restrict__ out)
{
    int i = blockIdx.x * blockDim.x + threadIdx.x;
    if (i < 2 * 2048 * 3) {
        int b = i / 6144;
        int rem = i - b * 6144;
        int n = rem / 3;
        int d = rem - n * 3;
        out[i] = pos[((size_t)b * 8192 + 4 * n) * 3 + d];
    }
}

// ---------------------------------------------------------------------------
extern "C" void kernel_launch(void* const* d_in, const int* in_sizes, int n_in,
                              void* d_out, int out_size)
{
    const float* pos  = (const float*)d_in[0];
    const float* ch   = (const float*)d_in[1];
    const float* W1   = (const float*)d_in[2];
    const float* b1   = (const float*)d_in[3];
    const float* Wres = (const float*)d_in[4];
    const float* bres = (const float*)d_in[5];
    const float* W2   = (const float*)d_in[6];
    const float* b2   = (const float*)d_in[7];
    const float* g1   = (const float*)d_in[8];
    const float* be1  = (const float*)d_in[9];
    const float* g2   = (const float*)d_in[10];
    const float* be2  = (const float*)d_in[11];
    float* out = (float*)d_out;

    int *knn1p, *knn2p;
    float *ch1p, *res1p;
    cudaGetSymbolAddress((void**)&knn1p, g_knn1);
    cudaGetSymbolAddress((void**)&knn2p, g_knn2);
    cudaGetSymbolAddress((void**)&ch1p, g_ch1);
    cudaGetSymbolAddress((void**)&res1p, g_res1);

    // stage-1 KNN: centers pos[:, ::2] vs all 8192 points
    knn_kernel<<<1024, 256>>>(pos, 1, 8192, 4096, knn1p);
    // stage-2 KNN: centers pos[:, ::4] vs points pos[:, ::2]
    knn_kernel<<<512, 256>>>(pos, 2, 4096, 2048, knn2p);
    // residual GEMM (stage 1)
    res_kernel<<<128, 128>>>(ch, Wres, bres, res1p);
    // conv1 + LN + SiLU -> ch1
    gconv_kernel<64, 64, 8, false><<<128, 128>>>(
        ch, knn1p, W1, b1, g1, be1, nullptr, ch1p, 8192, 4096);
    // conv2 + LN + SiLU + res1[:, ::2] -> output channels
    gconv_kernel<128, 32, 4, true><<<128, 128>>>(
        ch1p, knn2p, W2, b2, g2, be2, res1p, out + 2 * 2048 * 3, 4096, 2048);
    // pos output
    poscopy_kernel<<<48, 256>>>(pos, out);
}

// round 3
// speedup vs baseline: 2.8162x; 2.8162x over previous
#include <cuda_runtime.h>
#include <cstdint>
#include <cstddef>
#include <math.h>

// ---------------------------------------------------------------------------
// Scratch (device globals -- no allocation allowed)
// ---------------------------------------------------------------------------
__device__ int   g_knn1[2 * 4096 * 16];
__device__ int   g_knn2[2 * 2048 * 16];
__device__ float g_ch1 [2 * 4096 * 128];
__device__ float g_res1[2 * 4096 * 128];

// ---------------------------------------------------------------------------
// packed f32x2 helpers (sm_103a)
// ---------------------------------------------------------------------------
__device__ __forceinline__ unsigned long long pack2(float x, float y) {
    unsigned long long r;
    asm("mov.b64 %0, {%1, %2};" : "=l"(r) : "f"(x), "f"(y));
    return r;
}
__device__ __forceinline__ void fma2(unsigned long long& d,
                                     unsigned long long a,
                                     unsigned long long b) {
    asm("fma.rn.f32x2 %0, %1, %2, %0;" : "+l"(d) : "l"(a), "l"(b));
}

// ---------------------------------------------------------------------------
// KNN v2: warp-per-center, smem point tiles, warp-shared sorted top-16.
// Lanes 0..15 hold the current 16 best u64 keys ((dist_bits<<32)|idx) in
// ascending order; thresh = lane15's key. Scan: each lane evaluates one point
// per step; ballot gates a serialized shuffle-insert (rare after warmup).
// Exactly reproduces jax.lax.top_k(-d2) ordering (d asc, idx asc).
// ---------------------------------------------------------------------------
__global__ void __launch_bounds__(256) knn_kernel(
    const float* __restrict__ pos, int pstride,
    int n_in, int n_out, int* __restrict__ knn_out)
{
    constexpr int TILE = 1024;
    __shared__ float sp[3 * TILE + 2];      // xs @0, ys @TILE+1, zs @2*TILE+2
    float* sx = sp;
    float* sy = sp + TILE + 1;
    float* sz = sp + 2 * TILE + 2;

    const int tid  = threadIdx.x;
    const int warp = tid >> 5;
    const int lane = tid & 31;
    const int center = blockIdx.x * 8 + warp;   // 8 warps/block, same batch
    const int b = center / n_out;
    const int n = center % n_out;

    const float* posb = pos + (size_t)b * 8192 * 3;
    const float cx = posb[(size_t)(n * 2 * pstride) * 3 + 0];
    const float cy = posb[(size_t)(n * 2 * pstride) * 3 + 1];
    const float cz = posb[(size_t)(n * 2 * pstride) * 3 + 2];

    unsigned long long lkey  = ~0ull;   // sorted list in lanes 0..15
    unsigned long long thresh = ~0ull;  // = lane15 key

    const int nTiles = n_in / TILE;
    float v[12];                        // 3*TILE/256 floats per thread

    // prefetch tile 0
    {
        const int base = 0;
#pragma unroll
        for (int r = 0; r < 12; r++) {
            int i = r * 256 + tid;      // i in [0, 3*TILE)
            int p = i / 3, d = i - 3 * p;
            v[r] = __ldg(posb + (size_t)((base + p) * pstride) * 3 + d);
        }
    }

    for (int t = 0; t < nTiles; t++) {
        // stage prefetched tile into smem
#pragma unroll
        for (int r = 0; r < 12; r++) {
            int i = r * 256 + tid;
            int p = i / 3, d = i - 3 * p;
            sp[d * (TILE + 1) + p] = v[r];
        }
        __syncthreads();
        // prefetch next tile
        if (t + 1 < nTiles) {
            const int base = (t + 1) * TILE;
#pragma unroll
            for (int r = 0; r < 12; r++) {
                int i = r * 256 + tid;
                int p = i / 3, d = i - 3 * p;
                v[r] = __ldg(posb + (size_t)((base + p) * pstride) * 3 + d);
            }
        }
        // scan tile
        const int jbase = t * TILE;
#pragma unroll 4
        for (int it = 0; it < TILE / 32; ++it) {
            const int j = it * 32 + lane;
            float dx = __fadd_rn(cx, -sx[j]);
            float dy = __fadd_rn(cy, -sy[j]);
            float dz = __fadd_rn(cz, -sz[j]);
            // match reference rounding exactly: square each, left-to-right sum
            float d = __fadd_rn(__fadd_rn(__fmul_rn(dx, dx), __fmul_rn(dy, dy)),
                                __fmul_rn(dz, dz));
            unsigned long long key =
                ((unsigned long long)__float_as_uint(d) << 32) |
                (unsigned)(jbase + j);
            unsigned mask = __ballot_sync(0xffffffffu, key < thresh);
            while (mask) {
                int src = __ffs(mask) - 1;
                mask &= mask - 1;
                unsigned long long ck = __shfl_sync(0xffffffffu, key, src);
                if (ck < thresh) {   // recheck vs updated threshold (uniform)
                    unsigned long long up = __shfl_up_sync(0xffffffffu, lkey, 1);
                    bool keep = (lkey < ck);
                    unsigned long long ins = (lane == 0 || up < ck) ? ck : up;
                    lkey = keep ? lkey : ins;
                    thresh = __shfl_sync(0xffffffffu, lkey, 15);
                }
            }
        }
        __syncthreads();
    }

    if (lane < 16)
        knn_out[(size_t)center * 16 + lane] = (int)(unsigned)(lkey & 0xffffffffull);
}

// ---------------------------------------------------------------------------
// Gathered conv as tiled SGEMM (packed f32x2 FMA) + fused bias + LayerNorm +
// SiLU (+ residual). BN = 128 = full Cout so LN fuses in-block.
// ---------------------------------------------------------------------------
template <int CIN, int BM, int TM, bool HAS_RES>
__global__ void __launch_bounds__(128, 1)
gconv_kernel(const float* __restrict__ ch, const int* __restrict__ knn,
             const float* __restrict__ W, const float* __restrict__ bias,
             const float* __restrict__ gamma, const float* __restrict__ beta,
             const float* __restrict__ res_in, float* __restrict__ out,
             int n_in, int n_out)
{
    constexpr int BN = 128, BK = 16, TN = 8;
    constexpr int SA = BM + 4;
    constexpr int SB = BN + 4;
    constexpr int F = BM * BK / 128;
    constexpr int TPR = BK / F;
    constexpr int KD = 16 * CIN;
    constexpr int ITERS = CIN;          // KD / BK
    constexpr int LOADSZ = BK * SA + BK * SB;
    constexpr int SMEMSZ = (2 * LOADSZ > BM * BN) ? 2 * LOADSZ : BM * BN;
    __shared__ __align__(16) float sm[SMEMSZ];

    const int tid = threadIdx.x;
    const int m_base = blockIdx.x * BM;
    const int b = m_base / n_out;
    const int tc = tid & 15;
    const int tr = tid >> 4;
    const int arow = tid / TPR;
    const int aoff = (tid % TPR) * F;
    const int* knnrow = knn + (size_t)(m_base + arow) * 16;
    const float* chb = ch + (size_t)b * n_in * CIN;
    const float* Wr = W + (size_t)tid * KD;

    unsigned long long acc[TM][TN / 2];
#pragma unroll
    for (int i = 0; i < TM; i++)
#pragma unroll
        for (int j = 0; j < TN / 2; j++) acc[i][j] = 0ull;

    float ra[F], rb[16];

    auto loadA = [&](int it) {
        int kn = (it * BK) / CIN;
        int c0 = (it * BK) % CIN;
        int j = __ldg(&knnrow[kn]);
        const float* src = chb + (size_t)j * CIN + c0 + aoff;
#pragma unroll
        for (int i = 0; i < F; i += 4) {
            float4 vv = *(const float4*)(src + i);
            ra[i] = vv.x; ra[i + 1] = vv.y; ra[i + 2] = vv.z; ra[i + 3] = vv.w;
        }
    };
    auto loadB = [&](int it) {
        const float* src = Wr + it * BK;
#pragma unroll
        for (int i = 0; i < 16; i += 4) {
            float4 vv = *(const float4*)(src + i);
            rb[i] = vv.x; rb[i + 1] = vv.y; rb[i + 2] = vv.z; rb[i + 3] = vv.w;
        }
    };
    auto storeAB = [&](int buf) {
        float* As = sm + buf * LOADSZ;
        float* Bs = As + BK * SA;
#pragma unroll
        for (int i = 0; i < F; i++) As[(aoff + i) * SA + arow] = ra[i];
#pragma unroll
        for (int i = 0; i < 16; i++) Bs[i * SB + tid] = rb[i];
    };

    loadA(0); loadB(0); storeAB(0);
    __syncthreads();
    int cur = 0;

    for (int it = 0; it < ITERS; ++it) {
        if (it + 1 < ITERS) { loadA(it + 1); loadB(it + 1); }
        const float* As = sm + cur * LOADSZ;
        const float* Bs = As + BK * SA;
#pragma unroll
        for (int kk = 0; kk < BK; ++kk) {
            float a[TM];
#pragma unroll
            for (int i = 0; i < TM; i += 4) {
                float4 vv = *(const float4*)(As + kk * SA + tr * TM + i);
                a[i] = vv.x; a[i + 1] = vv.y; a[i + 2] = vv.z; a[i + 3] = vv.w;
            }
            unsigned long long bb[TN / 2];
            const ulonglong2* bp =
                (const ulonglong2*)(Bs + kk * SB + tc * TN);
            {
                ulonglong2 b0 = bp[0];
                ulonglong2 b1 = bp[1];
                bb[0] = b0.x; bb[1] = b0.y; bb[2] = b1.x; bb[3] = b1.y;
            }
#pragma unroll
            for (int i = 0; i < TM; i++) {
                unsigned long long ap = pack2(a[i], a[i]);
#pragma unroll
                for (int j = 0; j < TN / 2; j++) fma2(acc[i][j], ap, bb[j]);
            }
        }
        if (it + 1 < ITERS) {
            storeAB(cur ^ 1);
            __syncthreads();
            cur ^= 1;
        }
    }

    // ---- epilogue: bias + LayerNorm + SiLU (+ residual) ----
    __syncthreads();
    float* Cs = sm;
#pragma unroll
    for (int i = 0; i < TM; i++)
#pragma unroll
        for (int j = 0; j < TN / 2; j++) {
            float2 u = *(float2*)&acc[i][j];
            Cs[(tr * TM + i) * BN + tc * TN + 2 * j]     = u.x;
            Cs[(tr * TM + i) * BN + tc * TN + 2 * j + 1] = u.y;
        }
    __syncthreads();

    const int w = tid >> 5, lane = tid & 31;
    float4 bbv = *(const float4*)(bias + lane * 4);
    float4 gg = *(const float4*)(gamma + lane * 4);
    float4 be = *(const float4*)(beta + lane * 4);

    for (int r = w; r < BM; r += 4) {
        float4 x = *(float4*)(Cs + r * BN + lane * 4);
        x.x += bbv.x; x.y += bbv.y; x.z += bbv.z; x.w += bbv.w;

        float s = x.x + x.y + x.z + x.w;
#pragma unroll
        for (int off = 16; off; off >>= 1) s += __shfl_xor_sync(~0u, s, off);
        float mu = s * (1.0f / 128.0f);
        float d0 = x.x - mu, d1 = x.y - mu, d2v = x.z - mu, d3 = x.w - mu;
        float s2 = d0 * d0 + d1 * d1 + d2v * d2v + d3 * d3;
#pragma unroll
        for (int off = 16; off; off >>= 1) s2 += __shfl_xor_sync(~0u, s2, off);
        float rstd = rsqrtf(s2 * (1.0f / 128.0f) + 1e-5f);

        float y0 = d0 * rstd * gg.x + be.x;
        float y1 = d1 * rstd * gg.y + be.y;
        float y2 = d2v * rstd * gg.z + be.z;
        float y3 = d3 * rstd * gg.w + be.w;
        float4 o4;
        o4.x = y0 / (1.0f + expf(-y0));
        o4.y = y1 / (1.0f + expf(-y1));
        o4.z = y2 / (1.0f + expf(-y2));
        o4.w = y3 / (1.0f + expf(-y3));

        const int m = m_base + r;
        if (HAS_RES) {
            const int nn = m % n_out;
            const float4 rr = *(const float4*)(
                res_in + ((size_t)b * (2 * n_out) + 2 * nn) * BN + lane * 4);
            o4.x += rr.x; o4.y += rr.y; o4.z += rr.z; o4.w += rr.w;
        }
        *(float4*)(out + (size_t)m * BN + lane * 4) = o4;
    }
}

// ---------------------------------------------------------------------------
// Residual path (stage 1): res1[b,n,:] = ch[b,2n,:] @ Wres + bres
// ---------------------------------------------------------------------------
__global__ void __launch_bounds__(128) res_kernel(
    const float* __restrict__ ch, const float* __restrict__ Wres,
    const float* __restrict__ bres, float* __restrict__ res1)
{
    __shared__ float s_w[64 * 128];
    __shared__ float s_ch[8][64];
    const int tid = threadIdx.x;
    const int m_base = blockIdx.x * 64;
    const int b = m_base / 4096;
    const int n_base = m_base % 4096;

    for (int i = tid; i < 64 * 128 / 4; i += 128)
        ((float4*)s_w)[i] = ((const float4*)Wres)[i];
    __syncthreads();

    const float bias = __ldg(&bres[tid]);
    const int rr = tid >> 4, q = tid & 15;

    for (int g = 0; g < 8; g++) {
        const float* src = ch +
            ((size_t)b * 8192 + 2 * (n_base + g * 8 + rr)) * 64 + q * 4;
        *(float4*)&s_ch[rr][q * 4] = *(const float4*)src;
        __syncthreads();
        float acc[8];
#pragma unroll
        for (int t = 0; t < 8; t++) acc[t] = bias;
        for (int c = 0; c < 64; c++) {
            float wv = s_w[c * 128 + tid];
#pragma unroll
            for (int t = 0; t < 8; t++) acc[t] += s_ch[t][c] * wv;
        }
#pragma unroll
        for (int t = 0; t < 8; t++)
            res1[(size_t)(m_base + g * 8 + t) * 128 + tid] = acc[t];
        __syncthreads();
    }
}

// ---------------------------------------------------------------------------
__global__ void poscopy_kernel(const float* __restrict__ pos,
                               float* __restrict__ out)
{
    int i = blockIdx.x * blockDim.x + threadIdx.x;
    if (i < 2 * 2048 * 3) {
        int b = i / 6144;
        int rem = i - b * 6144;
        int n = rem / 3;
        int d = rem - n * 3;
        out[i] = pos[((size_t)b * 8192 + 4 * n) * 3 + d];
    }
}

// ---------------------------------------------------------------------------
extern "C" void kernel_launch(void* const* d_in, const int* in_sizes, int n_in,
                              void* d_out, int out_size)
{
    const float* pos  = (const float*)d_in[0];
    const float* ch   = (const float*)d_in[1];
    const float* W1   = (const float*)d_in[2];
    const float* b1   = (const float*)d_in[3];
    const float* Wres = (const float*)d_in[4];
    const float* bres = (const float*)d_in[5];
    const float* W2   = (const float*)d_in[6];
    const float* b2   = (const float*)d_in[7];
    const float* g1   = (const float*)d_in[8];
    const float* be1  = (const float*)d_in[9];
    const float* g2   = (const float*)d_in[10];
    const float* be2  = (const float*)d_in[11];
    float* out = (float*)d_out;

    int *knn1p, *knn2p;
    float *ch1p, *res1p;
    cudaGetSymbolAddress((void**)&knn1p, g_knn1);
    cudaGetSymbolAddress((void**)&knn2p, g_knn2);
    cudaGetSymbolAddress((void**)&ch1p, g_ch1);
    cudaGetSymbolAddress((void**)&res1p, g_res1);

    // stage-1 KNN: centers pos[:, ::2] vs all 8192 points
    knn_kernel<<<1024, 256>>>(pos, 1, 8192, 4096, knn1p);
    // stage-2 KNN: centers pos[:, ::4] vs points pos[:, ::2]
    knn_kernel<<<512, 256>>>(pos, 2, 4096, 2048, knn2p);
    // residual GEMM (stage 1)
    res_kernel<<<128, 128>>>(ch, Wres, bres, res1p);
    // conv1 + LN + SiLU -> ch1
    gconv_kernel<64, 64, 8, false><<<128, 128>>>(
        ch, knn1p, W1, b1, g1, be1, nullptr, ch1p, 8192, 4096);
    // conv2 + LN + SiLU + res1[:, ::2] -> output channels
    gconv_kernel<128, 32, 4, true><<<128, 128>>>(
        ch1p, knn2p, W2, b2, g2, be2, res1p, out + 2 * 2048 * 3, 4096, 2048);
    // pos output
    poscopy_kernel<<<48, 256>>>(pos, out);
}

// round 4
// speedup vs baseline: 3.6130x; 1.2830x over previous
#include <cuda_runtime.h>
#include <cstdint>
#include <cstddef>
#include <math.h>

// ---------------------------------------------------------------------------
// Scratch (device globals -- no allocation allowed)
// ---------------------------------------------------------------------------
__device__ int   g_knn1[2 * 4096 * 16];
__device__ int   g_knn2[2 * 2048 * 16];
__device__ float g_ch1 [2 * 4096 * 128];
__device__ float g_res1[2 * 4096 * 128];
__device__ float g_part[2 * 1048576];      // split-K partials (8MB)

// ---------------------------------------------------------------------------
// packed f32x2 helpers (sm_103a)
// ---------------------------------------------------------------------------
__device__ __forceinline__ unsigned long long pack2(float x, float y) {
    unsigned long long r;
    asm("mov.b64 %0, {%1, %2};" : "=l"(r) : "f"(x), "f"(y));
    return r;
}
__device__ __forceinline__ void fma2(unsigned long long& d,
                                     unsigned long long a,
                                     unsigned long long b) {
    asm("fma.rn.f32x2 %0, %1, %2, %0;" : "+l"(d) : "l"(a), "l"(b));
}

// ---------------------------------------------------------------------------
// KNN v3: warp-per-center, float4 smem tiles, 1 ballot per 4 points.
// Lanes 0..15 hold sorted top-16 u64 keys ((dist_bits<<32)|idx); thresh =
// lane15 key, tf = float image of its dist. Candidate filter: min of 4 dists
// <= tf (conservative, exact recheck in serialized insert). Reproduces
// jax.lax.top_k(-d2) ordering (d asc, idx asc) exactly.
// ---------------------------------------------------------------------------
__global__ void __launch_bounds__(256) knn_kernel(
    const float* __restrict__ pos, int pstride,
    int n_in, int n_out, int* __restrict__ knn_out)
{
    constexpr int TILE = 1024;
    __shared__ float4 sp[TILE];

    const int tid  = threadIdx.x;
    const int warp = tid >> 5;
    const int lane = tid & 31;
    const int center = blockIdx.x * 8 + warp;
    const int b = center / n_out;
    const int n = center % n_out;

    const float* posb = pos + (size_t)b * 8192 * 3;
    const float cx = posb[(size_t)(n * 2 * pstride) * 3 + 0];
    const float cy = posb[(size_t)(n * 2 * pstride) * 3 + 1];
    const float cz = posb[(size_t)(n * 2 * pstride) * 3 + 2];

    unsigned long long lkey   = 0x7F800000FFFFFFFFull;  // (+inf, max idx)
    unsigned long long thresh = 0x7F800000FFFFFFFFull;
    float tf = __int_as_float(0x7F800000);              // +inf

    const int nTiles = n_in / TILE;
    float v[12];

    // prefetch tile 0: point p = k*256 + tid
#pragma unroll
    for (int k = 0; k < 4; k++) {
        int p = k * 256 + tid;
#pragma unroll
        for (int d = 0; d < 3; d++)
            v[3 * k + d] = __ldg(posb + (size_t)p * pstride * 3 + d);
    }

    for (int t = 0; t < nTiles; t++) {
#pragma unroll
        for (int k = 0; k < 4; k++)
            sp[k * 256 + tid] = make_float4(v[3 * k], v[3 * k + 1],
                                            v[3 * k + 2], 0.0f);
        __syncthreads();
        if (t + 1 < nTiles) {
            const int base = (t + 1) * TILE;
#pragma unroll
            for (int k = 0; k < 4; k++) {
                int p = base + k * 256 + tid;
#pragma unroll
                for (int d = 0; d < 3; d++)
                    v[3 * k + d] = __ldg(posb + (size_t)p * pstride * 3 + d);
            }
        }

        const int jbase = t * TILE;
#pragma unroll
        for (int g = 0; g < 8; g++) {
            const int j0 = g * 128 + lane;
            float4 q0 = sp[j0];
            float4 q1 = sp[j0 + 32];
            float4 q2 = sp[j0 + 64];
            float4 q3 = sp[j0 + 96];
            // exact rounding: sub, square each (rn), left-to-right sum, no FMA
            float d0, d1, d2, d3;
            {
                float ax = __fadd_rn(cx, -q0.x), ay = __fadd_rn(cy, -q0.y), az = __fadd_rn(cz, -q0.z);
                d0 = __fadd_rn(__fadd_rn(__fmul_rn(ax, ax), __fmul_rn(ay, ay)), __fmul_rn(az, az));
            }
            {
                float ax = __fadd_rn(cx, -q1.x), ay = __fadd_rn(cy, -q1.y), az = __fadd_rn(cz, -q1.z);
                d1 = __fadd_rn(__fadd_rn(__fmul_rn(ax, ax), __fmul_rn(ay, ay)), __fmul_rn(az, az));
            }
            {
                float ax = __fadd_rn(cx, -q2.x), ay = __fadd_rn(cy, -q2.y), az = __fadd_rn(cz, -q2.z);
                d2 = __fadd_rn(__fadd_rn(__fmul_rn(ax, ax), __fmul_rn(ay, ay)), __fmul_rn(az, az));
            }
            {
                float ax = __fadd_rn(cx, -q3.x), ay = __fadd_rn(cy, -q3.y), az = __fadd_rn(cz, -q3.z);
                d3 = __fadd_rn(__fadd_rn(__fmul_rn(ax, ax), __fmul_rn(ay, ay)), __fmul_rn(az, az));
            }
            float dmin = fminf(fminf(d0, d1), fminf(d2, d3));
            unsigned mask = __ballot_sync(0xffffffffu, dmin <= tf);
            while (mask) {
                const int src = __ffs(mask) - 1;
                mask &= mask - 1;
                float dd0 = __shfl_sync(0xffffffffu, d0, src);
                float dd1 = __shfl_sync(0xffffffffu, d1, src);
                float dd2 = __shfl_sync(0xffffffffu, d2, src);
                float dd3 = __shfl_sync(0xffffffffu, d3, src);
                float dds[4] = {dd0, dd1, dd2, dd3};
#pragma unroll
                for (int tt = 0; tt < 4; tt++) {
                    unsigned idx = (unsigned)(jbase + g * 128 + tt * 32 + src);
                    unsigned long long ck =
                        ((unsigned long long)__float_as_uint(dds[tt]) << 32) | idx;
                    if (ck < thresh) {   // uniform branch
                        unsigned long long up = __shfl_up_sync(0xffffffffu, lkey, 1);
                        bool keep = (lkey < ck);
                        unsigned long long ins = (lane == 0 || up < ck) ? ck : up;
                        lkey = keep ? lkey : ins;
                        thresh = __shfl_sync(0xffffffffu, lkey, 15);
                        tf = __uint_as_float((unsigned)(thresh >> 32));
                    }
                }
            }
        }
        __syncthreads();
    }

    if (lane < 16)
        knn_out[(size_t)center * 16 + lane] =
            (int)(unsigned)(lkey & 0xffffffffull);
}

// ---------------------------------------------------------------------------
// Gathered-conv GEMM, split-K over neighbor groups. Writes fp32 partials.
// A[m][k*CIN+c] = ch[b, knn[m][k], c] gathered on the fly; B = W.
// ---------------------------------------------------------------------------
template <int CIN, int BM, int TM, int NSPLIT>
__global__ void __launch_bounds__(128, 2)
gconv_gemm(const float* __restrict__ ch, const int* __restrict__ knn,
           const float* __restrict__ W, float* __restrict__ part,
           int n_in, int n_out, int Mtot)
{
    constexpr int BN = 128, BK = 16, TN = 8;
    constexpr int SA = BM + 4;
    constexpr int SB = BN + 4;
    constexpr int F = BM * BK / 128;
    constexpr int TPR = BK / F;
    constexpr int NPB = 16 / NSPLIT;        // neighbors per split
    constexpr int ITERS = NPB * CIN / BK;
    constexpr int LOADSZ = BK * SA + BK * SB;
    __shared__ __align__(16) float sm[2 * LOADSZ];

    const int tid = threadIdx.x;
    const int split = blockIdx.y;
    const int m_base = blockIdx.x * BM;
    const int b = m_base / n_out;
    const int tc = tid & 15;
    const int tr = tid >> 4;
    const int arow = tid / TPR;
    const int aoff = (tid % TPR) * F;
    const int* knnrow = knn + (size_t)(m_base + arow) * 16;
    const float* chb = ch + (size_t)b * n_in * CIN;
    const float* Wr = W + (size_t)tid * (16 * CIN) + split * NPB * CIN;

    unsigned long long acc[TM][TN / 2];
#pragma unroll
    for (int i = 0; i < TM; i++)
#pragma unroll
        for (int j = 0; j < TN / 2; j++) acc[i][j] = 0ull;

    float ra[F], rb[16];

    auto loadA = [&](int it) {
        int kn = split * NPB + (it * BK) / CIN;
        int c0 = (it * BK) % CIN;
        int j = __ldg(&knnrow[kn]);
        const float* src = chb + (size_t)j * CIN + c0 + aoff;
#pragma unroll
        for (int i = 0; i < F; i += 4) {
            float4 vv = *(const float4*)(src + i);
            ra[i] = vv.x; ra[i + 1] = vv.y; ra[i + 2] = vv.z; ra[i + 3] = vv.w;
        }
    };
    auto loadB = [&](int it) {
        const float* src = Wr + it * BK;
#pragma unroll
        for (int i = 0; i < 16; i += 4) {
            float4 vv = *(const float4*)(src + i);
            rb[i] = vv.x; rb[i + 1] = vv.y; rb[i + 2] = vv.z; rb[i + 3] = vv.w;
        }
    };
    auto storeAB = [&](int buf) {
        float* As = sm + buf * LOADSZ;
        float* Bs = As + BK * SA;
#pragma unroll
        for (int i = 0; i < F; i++) As[(aoff + i) * SA + arow] = ra[i];
#pragma unroll
        for (int i = 0; i < 16; i++) Bs[i * SB + tid] = rb[i];
    };

    loadA(0); loadB(0); storeAB(0);
    __syncthreads();
    int cur = 0;

    for (int it = 0; it < ITERS; ++it) {
        if (it + 1 < ITERS) { loadA(it + 1); loadB(it + 1); }
        const float* As = sm + cur * LOADSZ;
        const float* Bs = As + BK * SA;
#pragma unroll
        for (int kk = 0; kk < BK; ++kk) {
            float a[TM];
#pragma unroll
            for (int i = 0; i < TM; i += 4) {
                float4 vv = *(const float4*)(As + kk * SA + tr * TM + i);
                a[i] = vv.x; a[i + 1] = vv.y; a[i + 2] = vv.z; a[i + 3] = vv.w;
            }
            unsigned long long bb[TN / 2];
            {
                const ulonglong2* bp = (const ulonglong2*)(Bs + kk * SB + tc * TN);
                ulonglong2 b0 = bp[0];
                ulonglong2 b1 = bp[1];
                bb[0] = b0.x; bb[1] = b0.y; bb[2] = b1.x; bb[3] = b1.y;
            }
#pragma unroll
            for (int i = 0; i < TM; i++) {
                unsigned long long ap = pack2(a[i], a[i]);
#pragma unroll
                for (int j = 0; j < TN / 2; j++) fma2(acc[i][j], ap, bb[j]);
            }
        }
        if (it + 1 < ITERS) {
            storeAB(cur ^ 1);
            __syncthreads();
            cur ^= 1;
        }
    }

    // write partials straight from registers (coalesced float4)
    float* dst = part + ((size_t)split * Mtot + m_base) * BN;
#pragma unroll
    for (int i = 0; i < TM; i++) {
        const int r = tr * TM + i;
        float2 u0 = *(float2*)&acc[i][0];
        float2 u1 = *(float2*)&acc[i][1];
        float2 u2 = *(float2*)&acc[i][2];
        float2 u3 = *(float2*)&acc[i][3];
        float4 w0 = make_float4(u0.x, u0.y, u1.x, u1.y);
        float4 w1 = make_float4(u2.x, u2.y, u3.x, u3.y);
        *(float4*)(dst + (size_t)r * BN + tc * TN)     = w0;
        *(float4*)(dst + (size_t)r * BN + tc * TN + 4) = w1;
    }
}

// ---------------------------------------------------------------------------
// Combine split-K partials + bias + LayerNorm + SiLU (+ residual).
// One warp per row (128 channels = 32 lanes x float4).
// ---------------------------------------------------------------------------
template <int NSPLIT, bool HAS_RES>
__global__ void __launch_bounds__(256) combine_kernel(
    const float* __restrict__ part, int M,
    const float* __restrict__ bias, const float* __restrict__ gamma,
    const float* __restrict__ beta, const float* __restrict__ res_in,
    float* __restrict__ out, int n_out)
{
    const int lane = threadIdx.x & 31;
    const int row = blockIdx.x * 8 + (threadIdx.x >> 5);

    const float4* p4 = (const float4*)part;
    float4 x = p4[(size_t)row * 32 + lane];
#pragma unroll
    for (int s = 1; s < NSPLIT; s++) {
        float4 y = p4[((size_t)s * M + row) * 32 + lane];
        x.x += y.x; x.y += y.y; x.z += y.z; x.w += y.w;
    }
    float4 bb = *(const float4*)(bias + lane * 4);
    float4 gg = *(const float4*)(gamma + lane * 4);
    float4 be = *(const float4*)(beta + lane * 4);
    x.x += bb.x; x.y += bb.y; x.z += bb.z; x.w += bb.w;

    float s = x.x + x.y + x.z + x.w;
#pragma unroll
    for (int off = 16; off; off >>= 1) s += __shfl_xor_sync(~0u, s, off);
    float mu = s * (1.0f / 128.0f);
    float d0 = x.x - mu, d1 = x.y - mu, d2 = x.z - mu, d3 = x.w - mu;
    float s2 = d0 * d0 + d1 * d1 + d2 * d2 + d3 * d3;
#pragma unroll
    for (int off = 16; off; off >>= 1) s2 += __shfl_xor_sync(~0u, s2, off);
    float rstd = rsqrtf(s2 * (1.0f / 128.0f) + 1e-5f);

    float y0 = d0 * rstd * gg.x + be.x;
    float y1 = d1 * rstd * gg.y + be.y;
    float y2 = d2 * rstd * gg.z + be.z;
    float y3 = d3 * rstd * gg.w + be.w;
    float4 o4;
    o4.x = y0 / (1.0f + expf(-y0));
    o4.y = y1 / (1.0f + expf(-y1));
    o4.z = y2 / (1.0f + expf(-y2));
    o4.w = y3 / (1.0f + expf(-y3));

    if (HAS_RES) {
        const int bb2 = row / n_out;
        const int nn = row % n_out;
        const float4 rr = *(const float4*)(
            res_in + ((size_t)bb2 * (2 * n_out) + 2 * nn) * 128 + lane * 4);
        o4.x += rr.x; o4.y += rr.y; o4.z += rr.z; o4.w += rr.w;
    }
    ((float4*)out)[(size_t)row * 32 + lane] = o4;
}

// ---------------------------------------------------------------------------
// Residual path (stage 1): res1[b,n,:] = ch[b,2n,:] @ Wres + bres
// ---------------------------------------------------------------------------
__global__ void __launch_bounds__(128) res_kernel(
    const float* __restrict__ ch, const float* __restrict__ Wres,
    const float* __restrict__ bres, float* __restrict__ res1)
{
    __shared__ float s_w[64 * 128];
    __shared__ float s_ch[8][64];
    const int tid = threadIdx.x;
    const int m_base = blockIdx.x * 64;
    const int b = m_base / 4096;
    const int n_base = m_base % 4096;

    for (int i = tid; i < 64 * 128 / 4; i += 128)
        ((float4*)s_w)[i] = ((const float4*)Wres)[i];
    __syncthreads();

    const float bias = __ldg(&bres[tid]);
    const int rr = tid >> 4, q = tid & 15;

    for (int g = 0; g < 8; g++) {
        const float* src = ch +
            ((size_t)b * 8192 + 2 * (n_base + g * 8 + rr)) * 64 + q * 4;
        *(float4*)&s_ch[rr][q * 4] = *(const float4*)src;
        __syncthreads();
        float acc[8];
#pragma unroll
        for (int t = 0; t < 8; t++) acc[t] = bias;
        for (int c = 0; c < 64; c++) {
            float wv = s_w[c * 128 + tid];
#pragma unroll
            for (int t = 0; t < 8; t++) acc[t] += s_ch[t][c] * wv;
        }
#pragma unroll
        for (int t = 0; t < 8; t++)
            res1[(size_t)(m_base + g * 8 + t) * 128 + tid] = acc[t];
        __syncthreads();
    }
}

// ---------------------------------------------------------------------------
__global__ void poscopy_kernel(const float* __restrict__ pos,
                               float* __restrict__ out)
{
    int i = blockIdx.x * blockDim.x + threadIdx.x;
    if (i < 2 * 2048 * 3) {
        int b = i / 6144;
        int rem = i - b * 6144;
        int n = rem / 3;
        int d = rem - n * 3;
        out[i] = pos[((size_t)b * 8192 + 4 * n) * 3 + d];
    }
}

// ---------------------------------------------------------------------------
extern "C" void kernel_launch(void* const* d_in, const int* in_sizes, int n_in,
                              void* d_out, int out_size)
{
    const float* pos  = (const float*)d_in[0];
    const float* ch   = (const float*)d_in[1];
    const float* W1   = (const float*)d_in[2];
    const float* b1   = (const float*)d_in[3];
    const float* Wres = (const float*)d_in[4];
    const float* bres = (const float*)d_in[5];
    const float* W2   = (const float*)d_in[6];
    const float* b2   = (const float*)d_in[7];
    const float* g1   = (const float*)d_in[8];
    const float* be1  = (const float*)d_in[9];
    const float* g2   = (const float*)d_in[10];
    const float* be2  = (const float*)d_in[11];
    float* out = (float*)d_out;

    int *knn1p, *knn2p;
    float *ch1p, *res1p, *partp;
    cudaGetSymbolAddress((void**)&knn1p, g_knn1);
    cudaGetSymbolAddress((void**)&knn2p, g_knn2);
    cudaGetSymbolAddress((void**)&ch1p, g_ch1);
    cudaGetSymbolAddress((void**)&res1p, g_res1);
    cudaGetSymbolAddress((void**)&partp, g_part);

    // KNN
    knn_kernel<<<1024, 256>>>(pos, 1, 8192, 4096, knn1p);
    knn_kernel<<<512, 256>>>(pos, 2, 4096, 2048, knn2p);
    // residual GEMM (stage 1)
    res_kernel<<<128, 128>>>(ch, Wres, bres, res1p);
    // conv1 split-K (2 splits of 8 neighbors) -> partials -> combine
    gconv_gemm<64, 64, 8, 2><<<dim3(128, 2), 128>>>(
        ch, knn1p, W1, partp, 8192, 4096, 8192);
    combine_kernel<2, false><<<1024, 256>>>(
        partp, 8192, b1, g1, be1, nullptr, ch1p, 4096);
    // conv2 split-K (4 splits of 4 neighbors) -> partials -> combine (+res)
    gconv_gemm<128, 64, 8, 4><<<dim3(64, 4), 128>>>(
        ch1p, knn2p, W2, partp, 4096, 2048, 4096);
    combine_kernel<4, true><<<512, 256>>>(
        partp, 4096, b2, g2, be2, res1p, out + 2 * 2048 * 3, 2048);
    // pos output
    poscopy_kernel<<<48, 256>>>(pos, out);
}

// round 5
// speedup vs baseline: 4.0156x; 1.1114x over previous
#include <cuda_runtime.h>
#include <cstdint>
#include <cstddef>
#include <math.h>

// ---------------------------------------------------------------------------
// Scratch (device globals -- no allocation allowed)
// ---------------------------------------------------------------------------
__device__ int   g_knn1[2 * 4096 * 16];
__device__ int   g_knn2[2 * 2048 * 16];
__device__ float g_ch1 [2 * 4096 * 128];
__device__ float g_res1[2 * 4096 * 128];
__device__ float g_part[2 * 1048576];      // split-K partials (8MB)

// ---------------------------------------------------------------------------
// tf32 helpers
// ---------------------------------------------------------------------------
__device__ __forceinline__ uint32_t to_tf32(float v) {
    uint32_t r;
    asm("cvt.rna.tf32.f32 %0, %1;" : "=r"(r) : "f"(v));
    return r;
}
__device__ __forceinline__ void split_tf32(float v, uint32_t& hi, uint32_t& lo) {
    hi = to_tf32(v);
    lo = to_tf32(v - __uint_as_float(hi));
}
__device__ __forceinline__ void mma_tf32(float c[4], const uint32_t a[4],
                                         const uint32_t b[2]) {
    asm("mma.sync.aligned.m16n8k8.row.col.f32.tf32.tf32.f32 "
        "{%0,%1,%2,%3}, {%4,%5,%6,%7}, {%8,%9}, {%0,%1,%2,%3};"
        : "+f"(c[0]), "+f"(c[1]), "+f"(c[2]), "+f"(c[3])
        : "r"(a[0]), "r"(a[1]), "r"(a[2]), "r"(a[3]), "r"(b[0]), "r"(b[1]));
}

// ---------------------------------------------------------------------------
// KNN v4: warp-per-center, float4 smem tiles, 1 ballot per distance slot.
// Lanes 0..15 hold sorted top-16 u64 keys ((dist_bits<<32)|idx); thresh =
// lane15 key, tf = float image of its dist. Reproduces jax.lax.top_k(-d2)
// ordering (d asc, idx asc) exactly (exact-rounded d2, no FMA contraction).
// ---------------------------------------------------------------------------
__global__ void __launch_bounds__(256) knn_kernel(
    const float* __restrict__ pos, int pstride,
    int n_in, int n_out, int* __restrict__ knn_out)
{
    constexpr int TILE = 1024;
    __shared__ float4 sp[TILE];

    const int tid  = threadIdx.x;
    const int warp = tid >> 5;
    const int lane = tid & 31;
    const int center = blockIdx.x * 8 + warp;
    const int b = center / n_out;
    const int n = center % n_out;

    const float* posb = pos + (size_t)b * 8192 * 3;
    const float cx = posb[(size_t)(n * 2 * pstride) * 3 + 0];
    const float cy = posb[(size_t)(n * 2 * pstride) * 3 + 1];
    const float cz = posb[(size_t)(n * 2 * pstride) * 3 + 2];

    unsigned long long lkey   = 0x7F800000FFFFFFFFull;  // (+inf, max idx)
    unsigned long long thresh = 0x7F800000FFFFFFFFull;
    float tf = __int_as_float(0x7F800000);              // +inf

    const int nTiles = n_in / TILE;
    float v[12];

#pragma unroll
    for (int k = 0; k < 4; k++) {
        int p = k * 256 + tid;
#pragma unroll
        for (int d = 0; d < 3; d++)
            v[3 * k + d] = __ldg(posb + (size_t)p * pstride * 3 + d);
    }

    for (int t = 0; t < nTiles; t++) {
#pragma unroll
        for (int k = 0; k < 4; k++)
            sp[k * 256 + tid] = make_float4(v[3 * k], v[3 * k + 1],
                                            v[3 * k + 2], 0.0f);
        __syncthreads();
        if (t + 1 < nTiles) {
            const int base = (t + 1) * TILE;
#pragma unroll
            for (int k = 0; k < 4; k++) {
                int p = base + k * 256 + tid;
#pragma unroll
                for (int d = 0; d < 3; d++)
                    v[3 * k + d] = __ldg(posb + (size_t)p * pstride * 3 + d);
            }
        }

        const int jbase = t * TILE;
#pragma unroll
        for (int g = 0; g < 8; g++) {
            const int j0 = g * 128 + lane;
            float dd[4];
#pragma unroll
            for (int q = 0; q < 4; q++) {
                float4 qq = sp[j0 + 32 * q];
                float ax = __fadd_rn(cx, -qq.x);
                float ay = __fadd_rn(cy, -qq.y);
                float az = __fadd_rn(cz, -qq.z);
                dd[q] = __fadd_rn(
                    __fadd_rn(__fmul_rn(ax, ax), __fmul_rn(ay, ay)),
                    __fmul_rn(az, az));
            }
#pragma unroll
            for (int q = 0; q < 4; q++) {
                unsigned mask = __ballot_sync(0xffffffffu, dd[q] <= tf);
                while (mask) {
                    const int src = __ffs(mask) - 1;
                    mask &= mask - 1;
                    float cd = __shfl_sync(0xffffffffu, dd[q], src);
                    unsigned idx = (unsigned)(jbase + g * 128 + q * 32 + src);
                    unsigned long long ck =
                        ((unsigned long long)__float_as_uint(cd) << 32) | idx;
                    if (ck < thresh) {   // uniform
                        unsigned long long up = __shfl_up_sync(0xffffffffu, lkey, 1);
                        bool keep = (lkey < ck);
                        unsigned long long ins = (lane == 0 || up < ck) ? ck : up;
                        lkey = keep ? lkey : ins;
                        thresh = __shfl_sync(0xffffffffu, lkey, 15);
                        tf = __uint_as_float((unsigned)(thresh >> 32));
                    }
                }
            }
        }
        __syncthreads();
    }

    if (lane < 16)
        knn_out[(size_t)center * 16 + lane] =
            (int)(unsigned)(lkey & 0xffffffffull);
}

// ---------------------------------------------------------------------------
// Gathered-conv GEMM on tensor cores (3xTF32, fp32 accumulate), split-K over
// neighbor groups. 128 threads = 4 warps; each warp owns a 32x64 C tile.
// A gathered on the fly into k-major smem [BK][BM+8]; B = W into [BK][BN+8].
// Pads SA=72 / SB=136 (== 8 mod 32) make all fragment LDS conflict-free.
// ---------------------------------------------------------------------------
template <int CIN, int NSPLIT>
__global__ void __launch_bounds__(128)
gconv_mma(const float* __restrict__ ch, const int* __restrict__ knn,
          const float* __restrict__ W, float* __restrict__ part,
          int n_in, int n_out, int Mtot)
{
    constexpr int BM = 64, BN = 128, BK = 16;
    constexpr int SA = 72, SB = 136;
    constexpr int NPB = 16 / NSPLIT;
    constexpr int ITERS = NPB * CIN / BK;
    constexpr int LOADSZ = BK * SA + BK * SB;
    __shared__ __align__(16) float sm[2 * LOADSZ];

    const int tid = threadIdx.x;
    const int split = blockIdx.y;
    const int m_base = blockIdx.x * BM;
    const int b = m_base / n_out;
    const int warp = tid >> 5, lane = tid & 31;
    const int g = lane >> 2, t = lane & 3;
    const int wm0 = (warp & 1) * 32, wn0 = (warp >> 1) * 64;

    const int arow = tid >> 1;
    const int aoff = (tid & 1) * 8;
    const int* knnrow = knn + (size_t)(m_base + arow) * 16;
    const float* chb = ch + (size_t)b * n_in * CIN;
    const float* Wr = W + (size_t)tid * (16 * CIN) + split * NPB * CIN;

    float acc[2][8][4];
#pragma unroll
    for (int i = 0; i < 2; i++)
#pragma unroll
        for (int j = 0; j < 8; j++)
#pragma unroll
            for (int k = 0; k < 4; k++) acc[i][j][k] = 0.0f;

    float ra[8], rb[16];

    auto loadA = [&](int it) {
        int kn = split * NPB + (it * BK) / CIN;
        int c0 = (it * BK) % CIN;
        int j = __ldg(&knnrow[kn]);
        const float* src = chb + (size_t)j * CIN + c0 + aoff;
#pragma unroll
        for (int i = 0; i < 8; i += 4) {
            float4 vv = *(const float4*)(src + i);
            ra[i] = vv.x; ra[i + 1] = vv.y; ra[i + 2] = vv.z; ra[i + 3] = vv.w;
        }
    };
    auto loadB = [&](int it) {
        const float* src = Wr + it * BK;
#pragma unroll
        for (int i = 0; i < 16; i += 4) {
            float4 vv = *(const float4*)(src + i);
            rb[i] = vv.x; rb[i + 1] = vv.y; rb[i + 2] = vv.z; rb[i + 3] = vv.w;
        }
    };
    auto storeAB = [&](int buf) {
        float* As = sm + buf * LOADSZ;
        float* Bs = As + BK * SA;
#pragma unroll
        for (int i = 0; i < 8; i++) As[(aoff + i) * SA + arow] = ra[i];
#pragma unroll
        for (int i = 0; i < 16; i++) Bs[i * SB + tid] = rb[i];
    };

    loadA(0); loadB(0); storeAB(0);
    __syncthreads();
    int cur = 0;

    for (int it = 0; it < ITERS; ++it) {
        if (it + 1 < ITERS) { loadA(it + 1); loadB(it + 1); }
        const float* As = sm + cur * LOADSZ;
        const float* Bs = As + BK * SA;
#pragma unroll
        for (int k0 = 0; k0 < BK; k0 += 8) {
            uint32_t Ab[2][4], Al[2][4];
#pragma unroll
            for (int mt = 0; mt < 2; mt++) {
                const int r0 = wm0 + mt * 16 + g;
                float v0 = As[(k0 + t) * SA + r0];
                float v1 = As[(k0 + t) * SA + r0 + 8];
                float v2 = As[(k0 + t + 4) * SA + r0];
                float v3 = As[(k0 + t + 4) * SA + r0 + 8];
                split_tf32(v0, Ab[mt][0], Al[mt][0]);
                split_tf32(v1, Ab[mt][1], Al[mt][1]);
                split_tf32(v2, Ab[mt][2], Al[mt][2]);
                split_tf32(v3, Ab[mt][3], Al[mt][3]);
            }
            uint32_t Bb[8][2], Bl[8][2];
#pragma unroll
            for (int nt = 0; nt < 8; nt++) {
                const int nn = wn0 + nt * 8 + g;
                float w0 = Bs[(k0 + t) * SB + nn];
                float w1 = Bs[(k0 + t + 4) * SB + nn];
                split_tf32(w0, Bb[nt][0], Bl[nt][0]);
                split_tf32(w1, Bb[nt][1], Bl[nt][1]);
            }
#pragma unroll
            for (int mt = 0; mt < 2; mt++)
#pragma unroll
                for (int nt = 0; nt < 8; nt++) {
                    mma_tf32(acc[mt][nt], Ab[mt], Bb[nt]);
                    mma_tf32(acc[mt][nt], Ab[mt], Bl[nt]);
                    mma_tf32(acc[mt][nt], Al[mt], Bb[nt]);
                }
        }
        if (it + 1 < ITERS) {
            storeAB(cur ^ 1);
            __syncthreads();
            cur ^= 1;
        }
    }

    // write partials (fp32) straight from fragments
    float* dst = part + ((size_t)split * Mtot + m_base) * BN;
#pragma unroll
    for (int mt = 0; mt < 2; mt++)
#pragma unroll
        for (int nt = 0; nt < 8; nt++) {
            const int r = wm0 + mt * 16 + g;
            const int c = wn0 + nt * 8 + 2 * t;
            *(float2*)(dst + (size_t)r * BN + c) =
                make_float2(acc[mt][nt][0], acc[mt][nt][1]);
            *(float2*)(dst + (size_t)(r + 8) * BN + c) =
                make_float2(acc[mt][nt][2], acc[mt][nt][3]);
        }
}

// ---------------------------------------------------------------------------
// Combine split-K partials + bias + LayerNorm + SiLU (+ residual).
// ---------------------------------------------------------------------------
template <int NSPLIT, bool HAS_RES>
__global__ void __launch_bounds__(256) combine_kernel(
    const float* __restrict__ part, int M,
    const float* __restrict__ bias, const float* __restrict__ gamma,
    const float* __restrict__ beta, const float* __restrict__ res_in,
    float* __restrict__ out, int n_out)
{
    const int lane = threadIdx.x & 31;
    const int row = blockIdx.x * 8 + (threadIdx.x >> 5);

    const float4* p4 = (const float4*)part;
    float4 x = p4[(size_t)row * 32 + lane];
#pragma unroll
    for (int s = 1; s < NSPLIT; s++) {
        float4 y = p4[((size_t)s * M + row) * 32 + lane];
        x.x += y.x; x.y += y.y; x.z += y.z; x.w += y.w;
    }
    float4 bb = *(const float4*)(bias + lane * 4);
    float4 gg = *(const float4*)(gamma + lane * 4);
    float4 be = *(const float4*)(beta + lane * 4);
    x.x += bb.x; x.y += bb.y; x.z += bb.z; x.w += bb.w;

    float s = x.x + x.y + x.z + x.w;
#pragma unroll
    for (int off = 16; off; off >>= 1) s += __shfl_xor_sync(~0u, s, off);
    float mu = s * (1.0f / 128.0f);
    float d0 = x.x - mu, d1 = x.y - mu, d2 = x.z - mu, d3 = x.w - mu;
    float s2 = d0 * d0 + d1 * d1 + d2 * d2 + d3 * d3;
#pragma unroll
    for (int off = 16; off; off >>= 1) s2 += __shfl_xor_sync(~0u, s2, off);
    float rstd = rsqrtf(s2 * (1.0f / 128.0f) + 1e-5f);

    float y0 = d0 * rstd * gg.x + be.x;
    float y1 = d1 * rstd * gg.y + be.y;
    float y2 = d2 * rstd * gg.z + be.z;
    float y3 = d3 * rstd * gg.w + be.w;
    float4 o4;
    o4.x = y0 / (1.0f + expf(-y0));
    o4.y = y1 / (1.0f + expf(-y1));
    o4.z = y2 / (1.0f + expf(-y2));
    o4.w = y3 / (1.0f + expf(-y3));

    if (HAS_RES) {
        const int bb2 = row / n_out;
        const int nn = row % n_out;
        const float4 rr = *(const float4*)(
            res_in + ((size_t)bb2 * (2 * n_out) + 2 * nn) * 128 + lane * 4);
        o4.x += rr.x; o4.y += rr.y; o4.z += rr.z; o4.w += rr.w;
    }
    ((float4*)out)[(size_t)row * 32 + lane] = o4;
}

// ---------------------------------------------------------------------------
// Residual path (stage 1): res1[b,n,:] = ch[b,2n,:] @ Wres + bres
// ---------------------------------------------------------------------------
__global__ void __launch_bounds__(128) res_kernel(
    const float* __restrict__ ch, const float* __restrict__ Wres,
    const float* __restrict__ bres, float* __restrict__ res1)
{
    __shared__ float s_w[64 * 128];
    __shared__ float s_ch[8][64];
    const int tid = threadIdx.x;
    const int m_base = blockIdx.x * 64;
    const int b = m_base / 4096;
    const int n_base = m_base % 4096;

    for (int i = tid; i < 64 * 128 / 4; i += 128)
        ((float4*)s_w)[i] = ((const float4*)Wres)[i];
    __syncthreads();

    const float bias = __ldg(&bres[tid]);
    const int rr = tid >> 4, q = tid & 15;

    for (int g = 0; g < 8; g++) {
        const float* src = ch +
            ((size_t)b * 8192 + 2 * (n_base + g * 8 + rr)) * 64 + q * 4;
        *(float4*)&s_ch[rr][q * 4] = *(const float4*)src;
        __syncthreads();
        float acc[8];
#pragma unroll
        for (int t = 0; t < 8; t++) acc[t] = bias;
        for (int c = 0; c < 64; c++) {
            float wv = s_w[c * 128 + tid];
#pragma unroll
            for (int t = 0; t < 8; t++) acc[t] += s_ch[t][c] * wv;
        }
#pragma unroll
        for (int t = 0; t < 8; t++)
            res1[(size_t)(m_base + g * 8 + t) * 128 + tid] = acc[t];
        __syncthreads();
    }
}

// ---------------------------------------------------------------------------
__global__ void poscopy_kernel(const float* __restrict__ pos,
                               float* __restrict__ out)
{
    int i = blockIdx.x * blockDim.x + threadIdx.x;
    if (i < 2 * 2048 * 3) {
        int b = i / 6144;
        int rem = i - b * 6144;
        int n = rem / 3;
        int d = rem - n * 3;
        out[i] = pos[((size_t)b * 8192 + 4 * n) * 3 + d];
    }
}

// ---------------------------------------------------------------------------
extern "C" void kernel_launch(void* const* d_in, const int* in_sizes, int n_in,
                              void* d_out, int out_size)
{
    const float* pos  = (const float*)d_in[0];
    const float* ch   = (const float*)d_in[1];
    const float* W1   = (const float*)d_in[2];
    const float* b1   = (const float*)d_in[3];
    const float* Wres = (const float*)d_in[4];
    const float* bres = (const float*)d_in[5];
    const float* W2   = (const float*)d_in[6];
    const float* b2   = (const float*)d_in[7];
    const float* g1   = (const float*)d_in[8];
    const float* be1  = (const float*)d_in[9];
    const float* g2   = (const float*)d_in[10];
    const float* be2  = (const float*)d_in[11];
    float* out = (float*)d_out;

    int *knn1p, *knn2p;
    float *ch1p, *res1p, *partp;
    cudaGetSymbolAddress((void**)&knn1p, g_knn1);
    cudaGetSymbolAddress((void**)&knn2p, g_knn2);
    cudaGetSymbolAddress((void**)&ch1p, g_ch1);
    cudaGetSymbolAddress((void**)&res1p, g_res1);
    cudaGetSymbolAddress((void**)&partp, g_part);

    // KNN
    knn_kernel<<<1024, 256>>>(pos, 1, 8192, 4096, knn1p);
    knn_kernel<<<512, 256>>>(pos, 2, 4096, 2048, knn2p);
    // residual GEMM (stage 1)
    res_kernel<<<128, 128>>>(ch, Wres, bres, res1p);
    // conv1 split-K (2 splits of 8 neighbors) -> partials -> combine
    gconv_mma<64, 2><<<dim3(128, 2), 128>>>(
        ch, knn1p, W1, partp, 8192, 4096, 8192);
    combine_kernel<2, false><<<1024, 256>>>(
        partp, 8192, b1, g1, be1, nullptr, ch1p, 4096);
    // conv2 split-K (4 splits of 4 neighbors) -> partials -> combine (+res)
    gconv_mma<128, 4><<<dim3(64, 4), 128>>>(
        ch1p, knn2p, W2, partp, 4096, 2048, 4096);
    combine_kernel<4, true><<<512, 256>>>(
        partp, 4096, b2, g2, be2, res1p, out + 2 * 2048 * 3, 2048);
    // pos output
    poscopy_kernel<<<48, 256>>>(pos, out);
}